// round 16
// baseline (speedup 1.0000x reference)
#include <cuda_runtime.h>
#include <cuda_fp16.h>
#include <math.h>

#define H      128
#define H3     384
#define BATCH  64
#define TT     2048
#define TILE   128   // time steps staged per smem chunk

// feat[b*256 + dir*128 + i] = mean over t of hidden state
__device__ float g_feat[BATCH * 2 * H];

__device__ __forceinline__ float ex2f(float x) {
    float r; asm("ex2.approx.ftz.f32 %0, %1;" : "=f"(r) : "f"(x)); return r;
}
__device__ __forceinline__ float rcpf(float x) {
    float r; asm("rcp.approx.ftz.f32 %0, %1;" : "=f"(r) : "f"(x)); return r;
}
#define L2E 1.4426950408889634f
__device__ __forceinline__ float ftanh(float x) {   // accurate path (MLP)
    return 2.0f * rcpf(1.0f + ex2f(-2.0f * L2E * x)) - 1.0f;
}

// HW tanh fp32 (MUFU-class, 16 cyc)
__device__ __forceinline__ float tanhf_hw(float x) {
    float r; asm("tanh.approx.f32 %0, %1;" : "=f"(r) : "f"(x)); return r;
}
// gate sigmoid via HW tanh: sig(x) = 0.5*tanh(0.5x) + 0.5
__device__ __forceinline__ float fsig_hw(float x) {
    return fmaf(0.5f, tanhf_hw(0.5f * x), 0.5f);
}

// One persistent block per (batch, direction). 128 threads; thread i owns
// unit i completely: all 3 gate columns, full k=128, weights as fp16x2 in
// registers (192 regs), HFMA2 dot (rt2). Gate chain + h-update path in
// fp32; h mirrored in smem as fp16 (dot operand) AND fp32 (update path).
// ONE __syncthreads per step, ping-pong.
__global__ void __launch_bounds__(H, 1) gru_persist_kernel(
    const float* __restrict__ y, const float* __restrict__ u,
    const float* __restrict__ Wi_f, const float* __restrict__ bi_f,
    const float* __restrict__ Wh_f, const float* __restrict__ bhn_f,
    const float* __restrict__ Wi_b, const float* __restrict__ bi_b,
    const float* __restrict__ Wh_b, const float* __restrict__ bhn_b)
{
    const int blk = blockIdx.x;        // 0..127
    const int b   = blk & (BATCH - 1);
    const int dir = blk >> 6;          // 0 = fwd, 1 = bwd
    const int i   = threadIdx.x;       // unit 0..127

    const float* Wi  = dir ? Wi_b  : Wi_f;
    const float* bi  = dir ? bi_b  : bi_f;
    const float* Wh  = dir ? Wh_b  : Wh_f;
    const float* bhn = dir ? bhn_b : bhn_f;

    // ---- register-resident recurrent weights, fp16 pairs along k ----
    __half2 wr[H / 2], wz[H / 2], wn[H / 2];
#pragma unroll
    for (int m = 0; m < H / 2; ++m) {
        const float* r0 = Wh + (size_t)(2 * m)     * H3;
        const float* r1 = Wh + (size_t)(2 * m + 1) * H3;
        wr[m] = __floats2half2_rn(r0[i],         r1[i]);
        wz[m] = __floats2half2_rn(r0[i + H],     r1[i + H]);
        wn[m] = __floats2half2_rn(r0[i + 2 * H], r1[i + 2 * H]);
    }

    // ---- shared state ----
    __shared__ __align__(16) __half h16_s[2][H];      // ping-pong h (fp16, dots)
    __shared__ __align__(16) float  h32_s[2][H];      // ping-pong h (fp32, update)
    __shared__ __align__(16) float4 yu_s[TILE * 2];   // per step: y(4)+u(4)
    __shared__ __align__(16) float4 wi4_s[2 * H3];    // Wi columns, 2 float4

    // stage Wi (thread i: its 3 columns)
#pragma unroll
    for (int g = 0; g < 3; ++g) {
        const int col = i + g * H;
        wi4_s[col]      = make_float4(Wi[0 * H3 + col], Wi[1 * H3 + col],
                                      Wi[2 * H3 + col], Wi[3 * H3 + col]);
        wi4_s[H3 + col] = make_float4(Wi[4 * H3 + col], Wi[5 * H3 + col],
                                      Wi[6 * H3 + col], Wi[7 * H3 + col]);
    }
    const float bir = bi[i], biz = bi[i + H], bin = bi[i + 2 * H];
    const float bhn_i = bhn[i];

    h16_s[0][i] = __float2half(0.0f);
    h32_s[0][i] = 0.0f;
    __syncthreads();

    float hsum = 0.0f;
    int p = 0;

    // preload chunk 0 inputs into regs
    float4 y4n, u4n;
    {
        const int tc0 = (dir ? (TT - TILE) : 0) + i;
        y4n = *(const float4*)(y + ((size_t)b * TT + tc0) * 4);
        u4n = *(const float4*)(u + ((size_t)b * TT + tc0) * 4);
    }

    const int nchunk = TT / TILE;
    for (int c = 0; c < nchunk; ++c) {
        // stage current chunk; prefetch next
        yu_s[2 * i]     = y4n;
        yu_s[2 * i + 1] = u4n;
        __syncthreads();
        if (c + 1 < nchunk) {
            const int t0n = (dir ? (TT - (c + 2) * TILE) : ((c + 1) * TILE)) + i;
            y4n = *(const float4*)(y + ((size_t)b * TT + t0n) * 4);
            u4n = *(const float4*)(u + ((size_t)b * TT + t0n) * 4);
        }

        const int tt0 = dir ? (TILE - 1) : 0;
        const int sgn = dir ? -1 : 1;

        for (int s = 0; s < TILE; ++s) {
            const int tt = tt0 + sgn * s;

            // ---- xw (fp32, independent of h; fills dot-window gaps) ----
            const float4 ya = yu_s[2 * tt];
            const float4 ub = yu_s[2 * tt + 1];
            const float4 war = wi4_s[i],          wbr = wi4_s[H3 + i];
            const float4 waz = wi4_s[i + H],      wbz = wi4_s[H3 + i + H];
            const float4 wan = wi4_s[i + 2 * H],  wbn = wi4_s[H3 + i + 2 * H];
            float xr = bir, xz = biz, xn = bin;
            xr = fmaf(ya.x, war.x, xr); xr = fmaf(ya.y, war.y, xr);
            xr = fmaf(ya.z, war.z, xr); xr = fmaf(ya.w, war.w, xr);
            xr = fmaf(ub.x, wbr.x, xr); xr = fmaf(ub.y, wbr.y, xr);
            xr = fmaf(ub.z, wbr.z, xr); xr = fmaf(ub.w, wbr.w, xr);
            xz = fmaf(ya.x, waz.x, xz); xz = fmaf(ya.y, waz.y, xz);
            xz = fmaf(ya.z, waz.z, xz); xz = fmaf(ya.w, waz.w, xz);
            xz = fmaf(ub.x, wbz.x, xz); xz = fmaf(ub.y, wbz.y, xz);
            xz = fmaf(ub.z, wbz.z, xz); xz = fmaf(ub.w, wbz.w, xz);
            xn = fmaf(ya.x, wan.x, xn); xn = fmaf(ya.y, wan.y, xn);
            xn = fmaf(ya.z, wan.z, xn); xn = fmaf(ya.w, wan.w, xn);
            xn = fmaf(ub.x, wbn.x, xn); xn = fmaf(ub.y, wbn.y, xn);
            xn = fmaf(ub.z, wbn.z, xn); xn = fmaf(ub.w, wbn.w, xn);

            // ---- fp16 dot: 3 gates x full k, HFMA2, 6 accumulators ----
            const uint4* hq = (const uint4*)h16_s[p];
            const __half2 zz = __floats2half2_rn(0.0f, 0.0f);
            __half2 ar0 = zz, ar1 = zz, az0 = zz, az1 = zz, an0 = zz, an1 = zz;
#pragma unroll
            for (int q = 0; q < 16; ++q) {
                const uint4 hv = hq[q];               // broadcast LDS.128
                const __half2 h0 = *(const __half2*)&hv.x;
                const __half2 h1 = *(const __half2*)&hv.y;
                const __half2 h2 = *(const __half2*)&hv.z;
                const __half2 h3 = *(const __half2*)&hv.w;
                ar0 = __hfma2(h0, wr[4 * q + 0], ar0);
                az0 = __hfma2(h0, wz[4 * q + 0], az0);
                an0 = __hfma2(h0, wn[4 * q + 0], an0);
                ar1 = __hfma2(h1, wr[4 * q + 1], ar1);
                az1 = __hfma2(h1, wz[4 * q + 1], az1);
                an1 = __hfma2(h1, wn[4 * q + 1], an1);
                ar0 = __hfma2(h2, wr[4 * q + 2], ar0);
                az0 = __hfma2(h2, wz[4 * q + 2], az0);
                an0 = __hfma2(h2, wn[4 * q + 2], an0);
                ar1 = __hfma2(h3, wr[4 * q + 3], ar1);
                az1 = __hfma2(h3, wz[4 * q + 3], az1);
                an1 = __hfma2(h3, wn[4 * q + 3], an1);
            }
            // fp32 final reduction (one fp16 add level, then convert)
            const float2 arf = __half22float2(__hadd2(ar0, ar1));
            const float2 azf = __half22float2(__hadd2(az0, az1));
            const float2 anf = __half22float2(__hadd2(an0, an1));
            const float dr = arf.x + arf.y;
            const float dz = azf.x + azf.y;
            const float dn = anf.x + anf.y;

            // ---- gates + update, all fp32 ----
            const float hold = h32_s[p][i];
            const float r = fsig_hw(xr + dr);
            const float z = fsig_hw(xz + dz);
            const float P = dn + bhn_i;
            const float arg = fmaf(r, P, xn);
            const float n   = tanhf_hw(arg);
            const float hn  = fmaf(z, hold - n, n);   // (1-z)n + z h
            h32_s[p ^ 1][i] = hn;
            h16_s[p ^ 1][i] = __float2half(hn);
            __syncthreads();                 // ONE barrier per step
            p ^= 1;
            hsum += hn;                      // fp32, off path
        }
    }

    g_feat[b * (2 * H) + dir * H + i] = hsum * (1.0f / (float)TT);
}

// MLP heads: 256 -> 128 -> 64 -> 20, tanh, tanh, linear. (accurate tanh)
__global__ void __launch_bounds__(128) mlp_kernel(
    const float* __restrict__ mW0, const float* __restrict__ mb0,
    const float* __restrict__ mW1, const float* __restrict__ mb1,
    const float* __restrict__ mW2, const float* __restrict__ mb2,
    const float* __restrict__ sW0, const float* __restrict__ sb0,
    const float* __restrict__ sW1, const float* __restrict__ sb1,
    const float* __restrict__ sW2, const float* __restrict__ sb2,
    float* __restrict__ out)
{
    const int b    = blockIdx.x & (BATCH - 1);
    const int head = blockIdx.x >> 6;
    const int j    = threadIdx.x;

    const float* W0 = head ? sW0 : mW0;
    const float* b0 = head ? sb0 : mb0;
    const float* W1 = head ? sW1 : mW1;
    const float* b1 = head ? sb1 : mb1;
    const float* W2 = head ? sW2 : mW2;
    const float* b2 = head ? sb2 : mb2;

    __shared__ float feat_s[256];
    __shared__ float h1_s[128];
    __shared__ float h2_s[64];

    feat_s[j]       = g_feat[b * 256 + j];
    feat_s[j + 128] = g_feat[b * 256 + j + 128];
    __syncthreads();

    {   // layer 0: 256 -> 128
        float acc = b0[j];
#pragma unroll 16
        for (int i = 0; i < 256; ++i)
            acc = fmaf(feat_s[i], __ldg(W0 + (size_t)i * 128 + j), acc);
        h1_s[j] = ftanh(acc);
    }
    __syncthreads();

    if (j < 64) {   // layer 1: 128 -> 64
        float acc = b1[j];
#pragma unroll 16
        for (int i = 0; i < 128; ++i)
            acc = fmaf(h1_s[i], __ldg(W1 + (size_t)i * 64 + j), acc);
        h2_s[j] = ftanh(acc);
    }
    __syncthreads();

    if (j < 20) {   // layer 2: 64 -> 20
        float acc = b2[j];
#pragma unroll
        for (int i = 0; i < 64; ++i)
            acc = fmaf(h2_s[i], __ldg(W2 + (size_t)i * 20 + j), acc);
        out[head * (BATCH * 20) + b * 20 + j] = acc;
    }
}

extern "C" void kernel_launch(void* const* d_in, const int* in_sizes, int n_in,
                              void* d_out, int out_size)
{
    const float* y     = (const float*)d_in[0];
    const float* u     = (const float*)d_in[1];
    const float* Wi_f  = (const float*)d_in[2];
    const float* bi_f  = (const float*)d_in[3];
    const float* Wh_f  = (const float*)d_in[4];
    const float* bhn_f = (const float*)d_in[5];
    const float* Wi_b  = (const float*)d_in[6];
    const float* bi_b  = (const float*)d_in[7];
    const float* Wh_b  = (const float*)d_in[8];
    const float* bhn_b = (const float*)d_in[9];
    const float* mW0   = (const float*)d_in[10];
    const float* mb0   = (const float*)d_in[11];
    const float* mW1   = (const float*)d_in[12];
    const float* mb1   = (const float*)d_in[13];
    const float* mW2   = (const float*)d_in[14];
    const float* mb2   = (const float*)d_in[15];
    const float* sW0   = (const float*)d_in[16];
    const float* sb0   = (const float*)d_in[17];
    const float* sW1   = (const float*)d_in[18];
    const float* sb1   = (const float*)d_in[19];
    const float* sW2   = (const float*)d_in[20];
    const float* sb2   = (const float*)d_in[21];

    gru_persist_kernel<<<BATCH * 2, H>>>(y, u, Wi_f, bi_f, Wh_f, bhn_f,
                                         Wi_b, bi_b, Wh_b, bhn_b);
    mlp_kernel<<<BATCH * 2, 128>>>(mW0, mb0, mW1, mb1, mW2, mb2,
                                   sW0, sb0, sW1, sb1, sW2, sb2,
                                   (float*)d_out);
}